// round 1
// baseline (speedup 1.0000x reference)
#include <cuda_runtime.h>

#define N_SRC 50000
#define N_DST 50000
#define D     128
#define K     8

// Scratch (no allocations allowed)
__device__ int g_out_deg[N_SRC];
__device__ int g_neg[N_DST];
__device__ int g_ptr[N_DST + 1];

__global__ void zero_kernel() {
    int i = blockIdx.x * blockDim.x + threadIdx.x;
    if (i < N_SRC) g_out_deg[i] = 0;
    if (i < N_DST) g_neg[i] = 0;
}

__global__ void count_kernel(const int* __restrict__ src_idx,
                             const int* __restrict__ dst_idx,
                             const int* __restrict__ category, int E) {
    int e = blockIdx.x * blockDim.x + threadIdx.x;
    if (e >= E) return;
    int s = src_idx[e];
    atomicAdd(&g_out_deg[s], 1);
    if (category[s] == -1) atomicAdd(&g_neg[dst_idx[e]], 1);
}

// ptr[n] = lower_bound(dst_idx, n)  (dst_idx is sorted). ptr[N_DST] = E.
__global__ void ptr_kernel(const int* __restrict__ dst_idx, int E) {
    int n = blockIdx.x * blockDim.x + threadIdx.x;
    if (n > N_DST) return;
    int lo = 0, hi = E;
    while (lo < hi) {
        int mid = (lo + hi) >> 1;
        if (__ldg(&dst_idx[mid]) < n) lo = mid + 1; else hi = mid;
    }
    g_ptr[n] = lo;
}

// One warp per dst node. Each lane owns 4 consecutive floats (float4) of the
// 128-wide row. Gathers h_src rows on the fly with src-side norm applied.
__global__ void __launch_bounds__(256)
main_kernel(const float* __restrict__ h_src,
            const float* __restrict__ unif,
            const int* __restrict__ src_idx,
            float* __restrict__ out, int E) {
    int warp = (blockIdx.x * blockDim.x + threadIdx.x) >> 5;
    int lane = threadIdx.x & 31;
    if (warp >= N_DST) return;
    int n = warp;

    int p0 = g_ptr[n];
    int p1 = g_ptr[n + 1];
    int deg = p1 - p0;
    bool use_full = (deg <= K) || (g_neg[n] > 0);

    float4 acc = make_float4(0.f, 0.f, 0.f, 0.f);

    if (use_full) {
        // deg <= K here (except exotic neg_in case) -> cheap full reduction
        for (int e = p0; e < p1; ++e) {
            int s = __ldg(&src_idx[e]);
            float w = rsqrtf((float)max(g_out_deg[s], 1));
            const float4* row = (const float4*)(h_src + (long long)s * D);
            float4 v = __ldg(&row[lane]);
            acc.x += v.x * w; acc.y += v.y * w; acc.z += v.z * w; acc.w += v.w * w;
        }
    } else {
        float fdeg = (float)deg;
        // Precompute the 8 edge ids first so the index loads batch (MLP)
        int eids[K];
        #pragma unroll
        for (int k = 0; k < K; ++k) {
            float u = __ldg(&unif[n * K + k]);
            int off = (int)floorf(u * fdeg);
            off = min(off, deg - 1);
            eids[k] = min(p0 + off, E - 1);
        }
        int srcs[K];
        #pragma unroll
        for (int k = 0; k < K; ++k) srcs[k] = __ldg(&src_idx[eids[k]]);
        float ws[K];
        #pragma unroll
        for (int k = 0; k < K; ++k) ws[k] = rsqrtf((float)max(g_out_deg[srcs[k]], 1));
        #pragma unroll
        for (int k = 0; k < K; ++k) {
            const float4* row = (const float4*)(h_src + (long long)srcs[k] * D);
            float4 v = __ldg(&row[lane]);
            float w = ws[k];
            acc.x += v.x * w; acc.y += v.y * w; acc.z += v.z * w; acc.w += v.w * w;
        }
    }

    float innorm = rsqrtf((float)max(deg, 1));
    float4 o;
    o.x = acc.x * innorm; o.y = acc.y * innorm;
    o.z = acc.z * innorm; o.w = acc.w * innorm;
    ((float4*)(out + (long long)n * D))[lane] = o;
}

extern "C" void kernel_launch(void* const* d_in, const int* in_sizes, int n_in,
                              void* d_out, int out_size) {
    const float* h_src    = (const float*)d_in[0];
    // d_in[1] = h_dst : unused by the reference computation
    const float* unif     = (const float*)d_in[2];
    const int*   src_idx  = (const int*)d_in[3];
    const int*   dst_idx  = (const int*)d_in[4];
    const int*   category = (const int*)d_in[5];
    float* out = (float*)d_out;

    int E = in_sizes[3];

    zero_kernel<<<(N_SRC + 255) / 256, 256>>>();
    count_kernel<<<(E + 255) / 256, 256>>>(src_idx, dst_idx, category, E);
    ptr_kernel<<<(N_DST + 1 + 255) / 256, 256>>>(dst_idx, E);
    int warps = N_DST;
    int blocks = (warps * 32 + 255) / 256;
    main_kernel<<<blocks, 256>>>(h_src, unif, src_idx, out, E);
}

// round 2
// speedup vs baseline: 1.0553x; 1.0553x over previous
#include <cuda_runtime.h>

#define N_SRC 50000
#define N_DST 50000
#define D     128
#define K     8

// Scratch (no allocations allowed)
__device__ int  g_out_deg[N_SRC];
__device__ int  g_neg[N_DST];
__device__ int  g_ptr[N_DST + 1];
__device__ int  g_cnt[N_DST];              // -1 = full path, 1 = sampled path
__device__ int2 g_pairs[N_DST * K];        // (src, __float_as_int(weight)) per (n,k)

// Kernel 1: zero counters + build CSR row pointers via binary search
// (ptr only depends on sorted dst_idx, so it can run before count)
__global__ void init_ptr_kernel(const int* __restrict__ dst_idx, int E) {
    int n = blockIdx.x * blockDim.x + threadIdx.x;
    if (n < N_SRC) g_out_deg[n] = 0;
    if (n < N_DST) g_neg[n] = 0;
    if (n <= N_DST) {
        int lo = 0, hi = E;
        while (lo < hi) {
            int mid = (lo + hi) >> 1;
            if (__ldg(&dst_idx[mid]) < n) lo = mid + 1; else hi = mid;
        }
        g_ptr[n] = lo;
    }
}

// Kernel 2: out-degree histogram + escape-hatch category counter
__global__ void count_kernel(const int* __restrict__ src_idx,
                             const int* __restrict__ dst_idx,
                             const int* __restrict__ category, int E) {
    int e = blockIdx.x * blockDim.x + threadIdx.x;
    if (e >= E) return;
    int s = src_idx[e];
    atomicAdd(&g_out_deg[s], 1);
    if (__ldg(&category[s]) == -1) atomicAdd(&g_neg[dst_idx[e]], 1);
}

// Kernel 3: resolve sampling per (node, k). One thread per (n,k); fully
// parallel, hides the ptr->unif->src_idx->out_deg chain behind 400k threads.
// Folds BOTH norms into the stored weight: w = out_deg^-0.5 * in_deg^-0.5.
__global__ void __launch_bounds__(256)
prep_kernel(const float* __restrict__ unif,
            const int* __restrict__ src_idx, int E) {
    int t = blockIdx.x * blockDim.x + threadIdx.x;
    if (t >= N_DST * K) return;
    int n = t >> 3;           // t / K
    int k = t & 7;            // t % K
    int p0 = __ldg(&g_ptr[n]);
    int p1 = __ldg(&g_ptr[n + 1]);
    int deg = p1 - p0;
    bool full = (deg <= K) || (__ldg(&g_neg[n]) > 0);
    if (k == 0) g_cnt[n] = full ? -1 : 1;
    if (full) return;

    float fdeg = (float)deg;
    float u = __ldg(&unif[t]);
    int off = (int)floorf(u * fdeg);
    off = min(off, deg - 1);
    int eid = min(p0 + off, E - 1);
    int s = __ldg(&src_idx[eid]);
    float w = rsqrtf((float)max(__ldg(&g_out_deg[s]), 1)) * rsqrtf(fdeg);
    g_pairs[t] = make_int2(s, __float_as_int(w));
}

// Kernel 4: one warp per dst node. Pairs are precomputed, so the only
// dependency is pairs -> 8 independent float4 gathers -> store.
__global__ void __launch_bounds__(256)
main_kernel(const float* __restrict__ h_src,
            const int* __restrict__ src_idx,
            float* __restrict__ out) {
    int warp = (blockIdx.x * blockDim.x + threadIdx.x) >> 5;
    int lane = threadIdx.x & 31;
    if (warp >= N_DST) return;
    int n = warp;

    float4 acc = make_float4(0.f, 0.f, 0.f, 0.f);
    int cnt = __ldg(&g_cnt[n]);

    if (cnt > 0) {
        // Sampled path: 4 broadcast int4 loads cover all 8 (src,w) pairs.
        const int4* pb = (const int4*)(g_pairs + n * K);
        int4 q0 = __ldg(&pb[0]);
        int4 q1 = __ldg(&pb[1]);
        int4 q2 = __ldg(&pb[2]);
        int4 q3 = __ldg(&pb[3]);
        int   srcs[K] = {q0.x, q0.z, q1.x, q1.z, q2.x, q2.z, q3.x, q3.z};
        float ws[K]   = {__int_as_float(q0.y), __int_as_float(q0.w),
                         __int_as_float(q1.y), __int_as_float(q1.w),
                         __int_as_float(q2.y), __int_as_float(q2.w),
                         __int_as_float(q3.y), __int_as_float(q3.w)};
        #pragma unroll
        for (int k = 0; k < K; ++k) {
            const float4* row = (const float4*)(h_src + (long long)srcs[k] * D);
            float4 v = __ldg(&row[lane]);
            float w = ws[k];
            acc.x += v.x * w; acc.y += v.y * w; acc.z += v.z * w; acc.w += v.w * w;
        }
        ((float4*)(out + (long long)n * D))[lane] = acc;
    } else {
        // Full path (deg <= K, or escape-hatch): loop edges directly.
        int p0 = __ldg(&g_ptr[n]);
        int p1 = __ldg(&g_ptr[n + 1]);
        int deg = p1 - p0;
        for (int e = p0; e < p1; ++e) {
            int s = __ldg(&src_idx[e]);
            float w = rsqrtf((float)max(__ldg(&g_out_deg[s]), 1));
            const float4* row = (const float4*)(h_src + (long long)s * D);
            float4 v = __ldg(&row[lane]);
            acc.x += v.x * w; acc.y += v.y * w; acc.z += v.z * w; acc.w += v.w * w;
        }
        float innorm = rsqrtf((float)max(deg, 1));
        float4 o;
        o.x = acc.x * innorm; o.y = acc.y * innorm;
        o.z = acc.z * innorm; o.w = acc.w * innorm;
        ((float4*)(out + (long long)n * D))[lane] = o;
    }
}

extern "C" void kernel_launch(void* const* d_in, const int* in_sizes, int n_in,
                              void* d_out, int out_size) {
    const float* h_src    = (const float*)d_in[0];
    // d_in[1] = h_dst : unused by the reference computation
    const float* unif     = (const float*)d_in[2];
    const int*   src_idx  = (const int*)d_in[3];
    const int*   dst_idx  = (const int*)d_in[4];
    const int*   category = (const int*)d_in[5];
    float* out = (float*)d_out;

    int E = in_sizes[3];

    init_ptr_kernel<<<(N_DST + 1 + 255) / 256, 256>>>(dst_idx, E);
    count_kernel<<<(E + 255) / 256, 256>>>(src_idx, dst_idx, category, E);
    prep_kernel<<<(N_DST * K + 255) / 256, 256>>>(unif, src_idx, E);
    main_kernel<<<(N_DST * 32 + 255) / 256, 256>>>(h_src, src_idx, out);
}

// round 3
// speedup vs baseline: 1.1841x; 1.1221x over previous
#include <cuda_runtime.h>

#define N_SRC 50000
#define N_DST 50000
#define D     128
#define K     8
#define NODES_PER_BLK 8

// Scratch (no allocations allowed). out_deg and neg fused for a single memset.
__device__ int g_counters[N_SRC + N_DST];   // [0,N_SRC)=out_deg, [N_SRC,..)=neg
__device__ int g_ptr[N_DST + 1];

// Kernel 1: out-degree histogram + escape-hatch counter + CSR ptr via
// boundary scan of the sorted dst_idx (no binary search, no extra launch).
__global__ void __launch_bounds__(256)
count_kernel(const int* __restrict__ src_idx,
             const int* __restrict__ dst_idx,
             const int* __restrict__ category, int E) {
    int e = blockIdx.x * blockDim.x + threadIdx.x;
    if (e >= E) return;
    int s = __ldg(&src_idx[e]);
    atomicAdd(&g_counters[s], 1);
    int cur = __ldg(&dst_idx[e]);
    if (__ldg(&category[s]) == -1) atomicAdd(&g_counters[N_SRC + cur], 1);
    // ptr[n] = lower_bound(dst_idx, n): for n in (dst[e-1], dst[e]] it's e.
    int prev = (e == 0) ? -1 : __ldg(&dst_idx[e - 1]);
    for (int d = prev + 1; d <= cur; ++d) g_ptr[d] = e;
    if (e == E - 1)
        for (int d = cur + 1; d <= N_DST; ++d) g_ptr[d] = E;
}

// Kernel 2: fused prep + gather. Block = 8 warps = 8 dst nodes.
// Phase 1: threads 0..63 resolve the 64 (node,k) samples into smem.
// Phase 2: warp-per-node, 8 independent float4 gathers + store.
__global__ void __launch_bounds__(256)
main_kernel(const float* __restrict__ h_src,
            const float* __restrict__ unif,
            const int* __restrict__ src_idx,
            float* __restrict__ out, int E) {
    __shared__ int  s_flag[NODES_PER_BLK];   // 1 = 8-pair path, -1 = fallback loop
    __shared__ int  s_p0[NODES_PER_BLK];
    __shared__ int  s_deg[NODES_PER_BLK];
    __shared__ int2 s_pairs[NODES_PER_BLK][K];

    int nbase = blockIdx.x * NODES_PER_BLK;   // grid is exactly N_DST/8 blocks
    int t = threadIdx.x;

    if (t < NODES_PER_BLK * K) {
        int nl = t >> 3;            // node within block
        int k  = t & 7;
        int n  = nbase + nl;
        int p0 = __ldg(&g_ptr[n]);
        int p1 = __ldg(&g_ptr[n + 1]);
        int deg = p1 - p0;
        int neg = __ldg(&g_counters[N_SRC + n]);
        bool small = (deg <= K);
        bool full  = small || (neg > 0);
        if (k == 0) {
            s_flag[nl] = (full && !small) ? -1 : 1;  // escape hatch only if deg>K
            s_p0[nl] = p0;
            s_deg[nl] = deg;
        }
        int eid = -1;
        if (!full) {
            float fdeg = (float)deg;
            float u = __ldg(&unif[n * K + k]);
            int off = min((int)floorf(u * fdeg), deg - 1);
            eid = min(p0 + off, E - 1);
        } else if (small && k < deg) {
            eid = p0 + k;           // full sum over the deg (<=8) edges
        }
        int2 pr = make_int2(0, 0);  // zero pad: gathers row 0 with weight 0
        if (eid >= 0) {
            int s = __ldg(&src_idx[eid]);
            float w = rsqrtf((float)max(__ldg(&g_counters[s]), 1)) *
                      rsqrtf((float)max(deg, 1));
            pr = make_int2(s, __float_as_int(w));
        }
        s_pairs[nl][k] = pr;
    }
    __syncthreads();

    int wid  = t >> 5;
    int lane = t & 31;
    int n = nbase + wid;
    float4 acc = make_float4(0.f, 0.f, 0.f, 0.f);

    if (s_flag[wid] > 0) {
        int   srcs[K];
        float ws[K];
        #pragma unroll
        for (int k = 0; k < K; ++k) {
            int2 pr = s_pairs[wid][k];
            srcs[k] = pr.x;
            ws[k] = __int_as_float(pr.y);
        }
        #pragma unroll
        for (int k = 0; k < K; ++k) {
            const float4* row = (const float4*)(h_src + (long long)srcs[k] * D);
            float4 v = __ldg(&row[lane]);
            float w = ws[k];
            acc.x += v.x * w; acc.y += v.y * w; acc.z += v.z * w; acc.w += v.w * w;
        }
        ((float4*)(out + (long long)n * D))[lane] = acc;
    } else {
        // Escape hatch (neg>0 && deg>K): full reduction over all edges.
        int p0 = s_p0[wid];
        int deg = s_deg[wid];
        for (int e = p0; e < p0 + deg; ++e) {
            int s = __ldg(&src_idx[e]);
            float w = rsqrtf((float)max(__ldg(&g_counters[s]), 1));
            const float4* row = (const float4*)(h_src + (long long)s * D);
            float4 v = __ldg(&row[lane]);
            acc.x += v.x * w; acc.y += v.y * w; acc.z += v.z * w; acc.w += v.w * w;
        }
        float innorm = rsqrtf((float)max(deg, 1));
        float4 o;
        o.x = acc.x * innorm; o.y = acc.y * innorm;
        o.z = acc.z * innorm; o.w = acc.w * innorm;
        ((float4*)(out + (long long)n * D))[lane] = o;
    }
}

extern "C" void kernel_launch(void* const* d_in, const int* in_sizes, int n_in,
                              void* d_out, int out_size) {
    const float* h_src    = (const float*)d_in[0];
    // d_in[1] = h_dst : unused by the reference computation
    const float* unif     = (const float*)d_in[2];
    const int*   src_idx  = (const int*)d_in[3];
    const int*   dst_idx  = (const int*)d_in[4];
    const int*   category = (const int*)d_in[5];
    float* out = (float*)d_out;

    int E = in_sizes[3];

    void* counters_ptr = nullptr;
    cudaGetSymbolAddress(&counters_ptr, g_counters);
    cudaMemsetAsync(counters_ptr, 0, (N_SRC + N_DST) * sizeof(int));

    count_kernel<<<(E + 255) / 256, 256>>>(src_idx, dst_idx, category, E);
    main_kernel<<<N_DST / NODES_PER_BLK, 256>>>(h_src, unif, src_idx, out, E);
}